// round 10
// baseline (speedup 1.0000x reference)
#include <cuda_runtime.h>
#include <cuda_bf16.h>

// Cross-head online Hadamard, float2 + warp-shuffle split.
//
// 32-point WHT across heads (stride 128 floats) for each (token, d).
// Each thread holds 16 heads (one half) for its float2 column:
//   lane = g*16 + dp   (g = head-half 0/1, dp = float2 column within chunk)
// Stages s=1,2,4,8 in registers; stage s=16 via shfl.xor(lane, 16).
// 32 data regs/thread -> ~2x occupancy vs the 64-reg all-register version.

#define HIDDEN     4096
#define NUM_HEADS  32
#define HEAD_DIM   128
#define H_HALF     16            // heads per thread
#define DP_PER_WARP 16           // float2 columns per warp chunk
#define WARPS_PER_TOK 4          // 4 chunks * 16 float2 = 64 float2 = 128 d
#define TOK_PER_BLOCK 2          // 8 warps = 256 threads

__global__ __launch_bounds__(256, 5)
void cross_head_hadamard_shfl_kernel(const float2* __restrict__ x,
                                     float2* __restrict__ y,
                                     int num_tokens)
{
    const int warp = threadIdx.x >> 5;
    const int lane = threadIdx.x & 31;
    const int g    = lane >> 4;          // head half: 0 or 1
    const int dp   = lane & 15;          // float2 column within chunk
    const int chunk = warp & 3;          // 0..3
    const int local_tok = warp >> 2;     // 0..1

    const long long t = (long long)blockIdx.x * TOK_PER_BLOCK + local_tok;
    if (t >= num_tokens) return;

    // float2-unit address of this thread's first element (head g*16 + 0)
    const long long base = t * (HIDDEN / 2)
                         + (long long)g * H_HALF * (HEAD_DIM / 2)
                         + chunk * DP_PER_WARP + dp;
    const float2* __restrict__ p = x + base;
    float2* __restrict__       q = y + base;

    float2 v[H_HALF];

    // 16 independent streaming loads (LDG.64), front-batched.
    #pragma unroll
    for (int j = 0; j < H_HALF; ++j)
        v[j] = __ldcs(p + j * (HEAD_DIM / 2));

    // In-register WHT stages s = 1,2,4,8 over the 16 contiguous heads.
    #pragma unroll
    for (int s = 1; s < H_HALF; s <<= 1) {
        #pragma unroll
        for (int j = 0; j < H_HALF; ++j) {
            if ((j & s) == 0) {
                const float2 a = v[j];
                const float2 b = v[j + s];
                v[j].x     = a.x + b.x;
                v[j].y     = a.y + b.y;
                v[j + s].x = a.x - b.x;
                v[j + s].y = a.y - b.y;
            }
        }
    }

    // Final stage s = 16: partner thread at lane ^ 16 holds the other half.
    // low half (g=0): new = v + other ; high half (g=1): new = other - v
    const float sgn = (g == 0) ? 1.0f : -1.0f;
    #pragma unroll
    for (int j = 0; j < H_HALF; ++j) {
        const float ox = __shfl_xor_sync(0xffffffffu, v[j].x, 16);
        const float oy = __shfl_xor_sync(0xffffffffu, v[j].y, 16);
        v[j].x = fmaf(sgn, v[j].x, ox);
        v[j].y = fmaf(sgn, v[j].y, oy);
    }

    const float scale = 0.17677669529663687f;  // 1/sqrt(32)

    #pragma unroll
    for (int j = 0; j < H_HALF; ++j) {
        float2 r;
        r.x = v[j].x * scale;
        r.y = v[j].y * scale;
        __stcs(q + j * (HEAD_DIM / 2), r);
    }
}

extern "C" void kernel_launch(void* const* d_in, const int* in_sizes, int n_in,
                              void* d_out, int out_size)
{
    const float2* x = (const float2*)d_in[0];
    float2*       y = (float2*)d_out;

    const int total_elems = in_sizes[0];           // 67,108,864
    const int num_tokens  = total_elems / HIDDEN;  // 16384

    const int blocks = (num_tokens + TOK_PER_BLOCK - 1) / TOK_PER_BLOCK;
    cross_head_hadamard_shfl_kernel<<<blocks, 256>>>(x, y, num_tokens);
}

// round 11
// speedup vs baseline: 1.0039x; 1.0039x over previous
#include <cuda_runtime.h>
#include <cuda_bf16.h>

// Cross-head online Hadamard, float2 + warp-shuffle split.
//
// 32-point WHT across heads (stride 128 floats) for each (token, d).
// Each thread holds 16 heads (one half) for its float2 column:
//   lane = g*16 + dp   (g = head-half 0/1, dp = float2 column within chunk)
// Stages s=1,2,4,8 in registers; stage s=16 via shfl.xor(lane, 16).
// 32 data regs/thread -> ~2x occupancy vs the 64-reg all-register version.

#define HIDDEN     4096
#define NUM_HEADS  32
#define HEAD_DIM   128
#define H_HALF     16            // heads per thread
#define DP_PER_WARP 16           // float2 columns per warp chunk
#define WARPS_PER_TOK 4          // 4 chunks * 16 float2 = 64 float2 = 128 d
#define TOK_PER_BLOCK 2          // 8 warps = 256 threads

__global__ __launch_bounds__(256, 5)
void cross_head_hadamard_shfl_kernel(const float2* __restrict__ x,
                                     float2* __restrict__ y,
                                     int num_tokens)
{
    const int warp = threadIdx.x >> 5;
    const int lane = threadIdx.x & 31;
    const int g    = lane >> 4;          // head half: 0 or 1
    const int dp   = lane & 15;          // float2 column within chunk
    const int chunk = warp & 3;          // 0..3
    const int local_tok = warp >> 2;     // 0..1

    const long long t = (long long)blockIdx.x * TOK_PER_BLOCK + local_tok;
    if (t >= num_tokens) return;

    // float2-unit address of this thread's first element (head g*16 + 0)
    const long long base = t * (HIDDEN / 2)
                         + (long long)g * H_HALF * (HEAD_DIM / 2)
                         + chunk * DP_PER_WARP + dp;
    const float2* __restrict__ p = x + base;
    float2* __restrict__       q = y + base;

    float2 v[H_HALF];

    // 16 independent streaming loads (LDG.64), front-batched.
    #pragma unroll
    for (int j = 0; j < H_HALF; ++j)
        v[j] = __ldcs(p + j * (HEAD_DIM / 2));

    // In-register WHT stages s = 1,2,4,8 over the 16 contiguous heads.
    #pragma unroll
    for (int s = 1; s < H_HALF; s <<= 1) {
        #pragma unroll
        for (int j = 0; j < H_HALF; ++j) {
            if ((j & s) == 0) {
                const float2 a = v[j];
                const float2 b = v[j + s];
                v[j].x     = a.x + b.x;
                v[j].y     = a.y + b.y;
                v[j + s].x = a.x - b.x;
                v[j + s].y = a.y - b.y;
            }
        }
    }

    // Final stage s = 16: partner thread at lane ^ 16 holds the other half.
    // low half (g=0): new = v + other ; high half (g=1): new = other - v
    const float sgn = (g == 0) ? 1.0f : -1.0f;
    #pragma unroll
    for (int j = 0; j < H_HALF; ++j) {
        const float ox = __shfl_xor_sync(0xffffffffu, v[j].x, 16);
        const float oy = __shfl_xor_sync(0xffffffffu, v[j].y, 16);
        v[j].x = fmaf(sgn, v[j].x, ox);
        v[j].y = fmaf(sgn, v[j].y, oy);
    }

    const float scale = 0.17677669529663687f;  // 1/sqrt(32)

    #pragma unroll
    for (int j = 0; j < H_HALF; ++j) {
        float2 r;
        r.x = v[j].x * scale;
        r.y = v[j].y * scale;
        __stcs(q + j * (HEAD_DIM / 2), r);
    }
}

extern "C" void kernel_launch(void* const* d_in, const int* in_sizes, int n_in,
                              void* d_out, int out_size)
{
    const float2* x = (const float2*)d_in[0];
    float2*       y = (float2*)d_out;

    const int total_elems = in_sizes[0];           // 67,108,864
    const int num_tokens  = total_elems / HIDDEN;  // 16384

    const int blocks = (num_tokens + TOK_PER_BLOCK - 1) / TOK_PER_BLOCK;
    cross_head_hadamard_shfl_kernel<<<blocks, 256>>>(x, y, num_tokens);
}